// round 4
// baseline (speedup 1.0000x reference)
#include <cuda_runtime.h>
#include <cuda_pipeline.h>

// Problem constants
#define NB   4096
#define NH   4096
#define HCD  16384
#define MIX  24

// Pass-1 tiling
#define BM     16     // batch rows per block
#define CH     64     // h per slab
#define HR     1024   // h range per block
#define NSLAB  16     // HR / CH
#define FN_LD  256    // fnS leading dim (no pad needed: reads are broadcast groups)
#define OUT_LD 264    // outS leading dim (padded, with xor swizzle)

// d_out layout: residual_cur | post_mix | comb_mix | layer_input
#define RES_OFF   0ULL
#define POST_OFF  67108864ULL                 // NB*4*NH
#define COMB_OFF  (POST_OFF + 16384ULL)       // + NB*4
#define LAYER_OFF (COMB_OFF + 65536ULL)       // + NB*16

// dynamic smem: fnS[2][24][256] | outS[16][264]  = 66048 B
#define FN_ELEMS   (2 * MIX * FN_LD)
#define OUT_ELEMS  (BM * OUT_LD)
#define SMEM_DYN   ((FN_ELEMS + OUT_ELEMS) * 4)

// Scratch (no allocations allowed -> __device__ globals)
__device__ float g_lp[4][NB][MIX];   // raw dot partials per h-split
__device__ float g_ssq[4][NB];       // sum-of-squares partials per h-split
__device__ float g_hpre[NB][4];      // softmax weights for pass 3

// ---------------------------------------------------------------------------
// Pass 1: residual_cur = comb@residual_prev + post*x ; write it out; fused
// accumulation of sumsq and 24 raw dot products with fn (pre-normalization).
//   - raw x/residual: one-slab-ahead REGISTER prefetch
//   - fn slab: cp.async double buffer
//   - acc tile [2][12] + dp=16 split -> 84-reg cap -> 3 blocks/SM (24 warps)
// Grid: (NB/BM, NH/HR) = (256, 4), 256 threads.
// ---------------------------------------------------------------------------
__global__ __launch_bounds__(256, 3) void k_pass1(
    const float* __restrict__ x, const float* __restrict__ rprev,
    const float* __restrict__ postp, const float* __restrict__ combp,
    const float* __restrict__ fn, float* __restrict__ out)
{
    extern __shared__ float smemf[];
    float (*fnS)[MIX][FN_LD] = (float (*)[MIX][FN_LD])smemf;
    float (*outS)[OUT_LD]    = (float (*)[OUT_LD])(smemf + FN_ELEMS);
    float (*red)[8]          = (float (*)[8])&outS[0][0];   // overlay, epilogue only

    __shared__ float comb_s[BM][16];
    __shared__ float post_s[BM][4];

    const int tid = threadIdx.x;
    const int b0  = blockIdx.x * BM;
    const int h0  = blockIdx.y * HR;

    for (int i = tid; i < BM * 16; i += 256)
        comb_s[i >> 4][i & 15] = combp[(size_t)(b0 + (i >> 4)) * 16 + (i & 15)];
    if (tid < BM * 4)
        post_s[tid >> 2][tid & 3] = postp[(size_t)b0 * 4 + tid];

    // compute-phase mapping: one float4-of-h per thread, fixed row
    const int crow = tid >> 4;             // 0..15
    const int ch4  = (tid & 15) << 2;      // 0..60
    // GEMM mapping: mg (m-half, 12 m's), rg (row pair, 8), dp (d-parallel, 16)
    const int mg = tid & 1;
    const int rg = (tid >> 1) & 7;
    const int dp = tid >> 4;               // 0..15

    const int bg = b0 + crow;
    const float* xrow = x + (size_t)bg * NH;
    const float* rrow = rprev + (size_t)bg * 4 * NH;
    float* orow = out + RES_OFF + (size_t)bg * 4 * NH;
    const int sw = (crow >> 2) << 2;       // bank-swizzle for outS

    // prologue: cp.async fn slab 0, register-load raw slab 0
    #pragma unroll
    for (int k = 0; k < 6; k++) {
        int i4 = tid + k * 256;            // 24 m * 64 float4
        int m  = i4 >> 6;
        int c4 = (i4 & 63) << 2;
        __pipeline_memcpy_async(&fnS[0][m][c4],
            fn + (size_t)m * HCD + (c4 >> 6) * NH + h0 + (c4 & 63), 16);
    }
    __pipeline_commit();

    float4 xv_p = *(const float4*)(xrow + h0 + ch4);
    float4 rv_p[4];
    #pragma unroll
    for (int j = 0; j < 4; j++)
        rv_p[j] = *(const float4*)(rrow + (size_t)j * NH + h0 + ch4);

    float acc[2][12];
    #pragma unroll
    for (int r = 0; r < 2; r++)
        #pragma unroll
        for (int mm = 0; mm < 12; mm++) acc[r][mm] = 0.f;
    float ssq = 0.f;

    for (int s = 0; s < NSLAB; s++) {
        const int st  = s & 1;
        const int hh0 = h0 + s * CH;

        __pipeline_wait_prior(0);   // fnS[st] landed (this thread)
        __syncthreads();            // all threads' fn writes + prior GEMM done

        // cp.async prefetch fn slab s+1 into the other stage
        if (s + 1 < NSLAB) {
            const int hh1 = hh0 + CH;
            #pragma unroll
            for (int k = 0; k < 6; k++) {
                int i4 = tid + k * 256;
                int m  = i4 >> 6;
                int c4 = (i4 & 63) << 2;
                __pipeline_memcpy_async(&fnS[st ^ 1][m][c4],
                    fn + (size_t)m * HCD + (c4 >> 6) * NH + hh1 + (c4 & 63), 16);
            }
            __pipeline_commit();
        }

        // compute residual_cur for (crow, 4n, 4h) from prefetched registers
        {
            const int hg = hh0 + ch4;
            #pragma unroll
            for (int n = 0; n < 4; n++) {
                const float ppn = post_s[crow][n];
                float4 o;
                o.x = ppn * xv_p.x; o.y = ppn * xv_p.y;
                o.z = ppn * xv_p.z; o.w = ppn * xv_p.w;
                #pragma unroll
                for (int j = 0; j < 4; j++) {
                    const float cbv = comb_s[crow][n * 4 + j];
                    o.x += cbv * rv_p[j].x; o.y += cbv * rv_p[j].y;
                    o.z += cbv * rv_p[j].z; o.w += cbv * rv_p[j].w;
                }
                *(float4*)(orow + (size_t)n * NH + hg) = o;
                *(float4*)&outS[crow][(n * CH + ch4) ^ sw] = o;
                ssq += o.x * o.x + o.y * o.y + o.z * o.z + o.w * o.w;
            }
        }

        // register prefetch of raw operands for slab s+1 (hidden by GEMM)
        if (s + 1 < NSLAB) {
            const int hg1 = hh0 + CH + ch4;
            xv_p = *(const float4*)(xrow + hg1);
            #pragma unroll
            for (int j = 0; j < 4; j++)
                rv_p[j] = *(const float4*)(rrow + (size_t)j * NH + hg1);
        }
        __syncthreads();

        // GEMM micro: acc[r][mm] += outS[rg*2+r][d] * fnS[m][d], d in dp's 16
        #pragma unroll
        for (int dd = 0; dd < 4; dd++) {
            const int d0 = dp * 16 + dd * 4;
            float4 o[2];
            #pragma unroll
            for (int r = 0; r < 2; r++) {
                const int rr = rg * 2 + r;
                o[r] = *(const float4*)&outS[rr][d0 ^ ((rr >> 2) << 2)];
            }
            #pragma unroll
            for (int mm = 0; mm < 12; mm++) {
                float4 f = *(const float4*)&fnS[st][mg * 12 + mm][d0];
                #pragma unroll
                for (int r = 0; r < 2; r++)
                    acc[r][mm] += o[r].x * f.x + o[r].y * f.y + o[r].z * f.z + o[r].w * f.w;
            }
        }
    }

    // --- dot reductions: dp bit4 in-warp shuffle, then 8 warps via smem
    #pragma unroll
    for (int r = 0; r < 2; r++)
        #pragma unroll
        for (int mm = 0; mm < 12; mm++) {
            float v = acc[r][mm];
            v += __shfl_xor_sync(0xffffffffu, v, 16);
            acc[r][mm] = v;
        }
    __syncthreads();   // everyone done reading outS before red overlay writes
    if ((tid & 16) == 0) {
        const int w = tid >> 5;
        #pragma unroll
        for (int r = 0; r < 2; r++)
            #pragma unroll
            for (int mm = 0; mm < 12; mm++)
                red[(mg * 12 + mm) * 16 + rg * 2 + r][w] = acc[r][mm];
    }
    __syncthreads();
    for (int o = tid; o < 384; o += 256) {
        float v = 0.f;
        #pragma unroll
        for (int w = 0; w < 8; w++) v += red[o][w];
        const int m = o >> 4, r = o & 15;
        g_lp[blockIdx.y][b0 + r][m] = v;
    }

    // --- sumsq: 16 lanes share crow
    float v = ssq;
    v += __shfl_xor_sync(0xffffffffu, v, 1);
    v += __shfl_xor_sync(0xffffffffu, v, 2);
    v += __shfl_xor_sync(0xffffffffu, v, 4);
    v += __shfl_xor_sync(0xffffffffu, v, 8);
    if ((tid & 15) == 0) g_ssq[blockIdx.y][bg] = v;
}

// ---------------------------------------------------------------------------
// Pass 2: per-row finalize — rms, softmax, sigmoid, Sinkhorn. One thread / row.
// ---------------------------------------------------------------------------
__global__ __launch_bounds__(256) void k_mid(
    const float* __restrict__ base, const float* __restrict__ scale,
    float* __restrict__ out)
{
    const int b = blockIdx.x * 256 + threadIdx.x;
    if (b >= NB) return;

    float lg[MIX];
    #pragma unroll
    for (int m = 0; m < MIX; m++)
        lg[m] = g_lp[0][b][m] + g_lp[1][b][m] + g_lp[2][b][m] + g_lp[3][b][m];
    const float ss = g_ssq[0][b] + g_ssq[1][b] + g_ssq[2][b] + g_ssq[3][b];
    const float inv = rsqrtf(ss * (1.0f / HCD) + 1e-6f);

    const float s0 = scale[0], s1 = scale[1], s2 = scale[2];

    // h_pre = softmax(logits[:4]*s0 + base[:4])
    float pre[4], mx = -1e30f;
    #pragma unroll
    for (int i = 0; i < 4; i++) {
        pre[i] = lg[i] * inv * s0 + base[i];
        mx = fmaxf(mx, pre[i]);
    }
    float e[4], den = 0.f;
    #pragma unroll
    for (int i = 0; i < 4; i++) { e[i] = expf(pre[i] - mx); den += e[i]; }
    const float rden = 1.f / den;
    #pragma unroll
    for (int i = 0; i < 4; i++) g_hpre[b][i] = e[i] * rden;

    // post_mix = sigmoid(logits[4:8]*s1 + base[4:8])
    #pragma unroll
    for (int i = 0; i < 4; i++) {
        const float p = lg[4 + i] * inv * s1 + base[4 + i];
        out[POST_OFF + (size_t)b * 4 + i] = 1.f / (1.f + expf(-p));
    }

    // comb_mix: Sinkhorn-Knopp on exp(logits[8:24]*s2 + base[8:24])
    float M[4][4];
    #pragma unroll
    for (int i = 0; i < 4; i++)
        #pragma unroll
        for (int j = 0; j < 4; j++)
            M[i][j] = expf(lg[8 + i * 4 + j] * inv * s2 + base[8 + i * 4 + j]);
    #pragma unroll
    for (int it = 0; it < 10; it++) {
        #pragma unroll
        for (int i = 0; i < 4; i++) {
            const float r = 1.f / (M[i][0] + M[i][1] + M[i][2] + M[i][3] + 1e-6f);
            #pragma unroll
            for (int j = 0; j < 4; j++) M[i][j] *= r;
        }
        #pragma unroll
        for (int j = 0; j < 4; j++) {
            const float c = 1.f / (M[0][j] + M[1][j] + M[2][j] + M[3][j] + 1e-6f);
            #pragma unroll
            for (int i = 0; i < 4; i++) M[i][j] *= c;
        }
    }
    #pragma unroll
    for (int i = 0; i < 4; i++)
        #pragma unroll
        for (int j = 0; j < 4; j++)
            out[COMB_OFF + (size_t)b * 16 + i * 4 + j] = M[i][j];
}

// ---------------------------------------------------------------------------
// Pass 3: layer_input[b,h] = sum_n h_pre[b,n] * residual_cur[b,n,h]
// ---------------------------------------------------------------------------
__global__ __launch_bounds__(256) void k_layer(float* __restrict__ out)
{
    const int b = blockIdx.x;
    const int h = (blockIdx.y * 256 + threadIdx.x) << 2;
    const float h0 = g_hpre[b][0], h1 = g_hpre[b][1];
    const float h2 = g_hpre[b][2], h3 = g_hpre[b][3];
    const float* rp = out + RES_OFF + (size_t)b * 4 * NH;
    const float4 a0 = *(const float4*)(rp + h);
    const float4 a1 = *(const float4*)(rp + NH + h);
    const float4 a2 = *(const float4*)(rp + 2 * NH + h);
    const float4 a3 = *(const float4*)(rp + 3 * NH + h);
    float4 o;
    o.x = h0 * a0.x + h1 * a1.x + h2 * a2.x + h3 * a3.x;
    o.y = h0 * a0.y + h1 * a1.y + h2 * a2.y + h3 * a3.y;
    o.z = h0 * a0.z + h1 * a1.z + h2 * a2.z + h3 * a3.z;
    o.w = h0 * a0.w + h1 * a1.w + h2 * a2.w + h3 * a3.w;
    *(float4*)(out + LAYER_OFF + (size_t)b * NH + h) = o;
}

extern "C" void kernel_launch(void* const* d_in, const int* in_sizes, int n_in,
                              void* d_out, int out_size)
{
    const float* x     = (const float*)d_in[0];
    const float* rprev = (const float*)d_in[1];
    const float* postp = (const float*)d_in[2];
    const float* combp = (const float*)d_in[3];
    const float* fn    = (const float*)d_in[4];
    const float* base  = (const float*)d_in[5];
    const float* scale = (const float*)d_in[6];
    float* out = (float*)d_out;

    cudaFuncSetAttribute(k_pass1, cudaFuncAttributeMaxDynamicSharedMemorySize, SMEM_DYN);
    k_pass1<<<dim3(NB / BM, NH / HR), 256, SMEM_DYN>>>(x, rprev, postp, combp, fn, out);
    k_mid<<<NB / 256, 256>>>(base, scale, out);
    k_layer<<<dim3(NB, NH / 1024), 256>>>(out);
}

// round 5
// speedup vs baseline: 1.2969x; 1.2969x over previous
#include <cuda_runtime.h>
#include <cuda_pipeline.h>

// Problem constants
#define NB   4096
#define NH   4096
#define HCD  16384
#define MIX  24

// Pass-1 tiling
#define BM     16     // batch rows per block
#define CH     64     // h per slab
#define HR     1024   // h range per block
#define NSLAB  16     // HR / CH
#define FN_LD  260    // fnS leading dim (padded)
#define OUT_LD 264    // outS leading dim (padded)

// d_out layout: residual_cur | post_mix | comb_mix | layer_input
#define RES_OFF   0ULL
#define POST_OFF  67108864ULL                 // NB*4*NH
#define COMB_OFF  (POST_OFF + 16384ULL)       // + NB*4
#define LAYER_OFF (COMB_OFF + 65536ULL)       // + NB*16

// dynamic smem: fnS[2][24][260] | outS[2][16][264]
#define FN_ELEMS   (2 * MIX * FN_LD)
#define OUT_ELEMS  (2 * BM * OUT_LD)
#define SMEM_DYN   ((FN_ELEMS + OUT_ELEMS) * 4)

// Scratch (no allocations allowed -> __device__ globals)
__device__ float g_lp[4][NB][MIX];   // raw dot partials per h-split
__device__ float g_ssq[4][NB];       // sum-of-squares partials per h-split
__device__ float g_hpre[NB][4];      // softmax weights for pass 3

// ---------------------------------------------------------------------------
// Pass 1: residual_cur = comb@residual_prev + post*x ; write it out; fused
// accumulation of sumsq and 24 raw dot products with fn (pre-normalization).
//   - raw x/residual: one-slab-ahead REGISTER prefetch (ldcs streaming)
//   - fn slab: cp.async double buffer (prefetch issued post-barrier)
//   - outS double buffered -> ONE __syncthreads per slab
// Grid: (NB/BM, NH/HR) = (256, 4), 256 threads, 2 blocks/SM.
// ---------------------------------------------------------------------------
__global__ __launch_bounds__(256, 2) void k_pass1(
    const float* __restrict__ x, const float* __restrict__ rprev,
    const float* __restrict__ postp, const float* __restrict__ combp,
    const float* __restrict__ fn, float* __restrict__ out)
{
    extern __shared__ float smemf[];
    float (*fnS)[MIX][FN_LD]     = (float (*)[MIX][FN_LD])smemf;
    float (*outS)[BM][OUT_LD]    = (float (*)[BM][OUT_LD])(smemf + FN_ELEMS);
    float (*red)[8]              = (float (*)[8])&outS[0][0][0]; // overlay, epilogue only

    __shared__ float comb_s[BM][16];
    __shared__ float post_s[BM][4];

    const int tid = threadIdx.x;
    const int b0  = blockIdx.x * BM;
    const int h0  = blockIdx.y * HR;

    for (int i = tid; i < BM * 16; i += 256)
        comb_s[i >> 4][i & 15] = combp[(size_t)(b0 + (i >> 4)) * 16 + (i & 15)];
    if (tid < BM * 4)
        post_s[tid >> 2][tid & 3] = postp[(size_t)b0 * 4 + tid];

    // compute-phase mapping: one float4-of-h per thread, fixed row
    const int crow = tid >> 4;             // 0..15
    const int ch4  = (tid & 15) << 2;      // 0..60
    // GEMM mapping: mg (m-half), rg (row group of 4), dp (d-parallel)
    const int mg = tid & 1;
    const int rg = (tid >> 1) & 3;
    const int dp = tid >> 3;               // 0..31

    const int bg = b0 + crow;
    const float* xrow = x + (size_t)bg * NH;
    const float* rrow = rprev + (size_t)bg * 4 * NH;
    float* orow = out + RES_OFF + (size_t)bg * 4 * NH;
    const int sw = (crow >> 2) << 2;       // bank-swizzle for outS

    // prologue: cp.async fn slab 0, register-load raw slab 0
    #pragma unroll
    for (int k = 0; k < 6; k++) {
        int i4 = tid + k * 256;            // 24 m * 64 float4
        int m  = i4 >> 6;
        int c4 = (i4 & 63) << 2;
        __pipeline_memcpy_async(&fnS[0][m][c4],
            fn + (size_t)m * HCD + (c4 >> 6) * NH + h0 + (c4 & 63), 16);
    }
    __pipeline_commit();

    float4 xv_p = __ldcs((const float4*)(xrow + h0 + ch4));
    float4 rv_p[4];
    #pragma unroll
    for (int j = 0; j < 4; j++)
        rv_p[j] = __ldcs((const float4*)(rrow + (size_t)j * NH + h0 + ch4));

    float acc[4][12];
    #pragma unroll
    for (int r = 0; r < 4; r++)
        #pragma unroll
        for (int mm = 0; mm < 12; mm++) acc[r][mm] = 0.f;
    float ssq = 0.f;

    __syncthreads();   // comb_s/post_s visible

    for (int s = 0; s < NSLAB; s++) {
        const int st  = s & 1;
        const int hh0 = h0 + s * CH;

        // ---- A phase: residual compute from prefetched registers
        {
            const int hg = hh0 + ch4;
            #pragma unroll
            for (int n = 0; n < 4; n++) {
                const float ppn = post_s[crow][n];
                float4 o;
                o.x = ppn * xv_p.x; o.y = ppn * xv_p.y;
                o.z = ppn * xv_p.z; o.w = ppn * xv_p.w;
                #pragma unroll
                for (int j = 0; j < 4; j++) {
                    const float cbv = comb_s[crow][n * 4 + j];
                    o.x += cbv * rv_p[j].x; o.y += cbv * rv_p[j].y;
                    o.z += cbv * rv_p[j].z; o.w += cbv * rv_p[j].w;
                }
                __stcs((float4*)(orow + (size_t)n * NH + hg), o);
                *(float4*)&outS[st][crow][(n * CH + ch4) ^ sw] = o;
                ssq += o.x * o.x + o.y * o.y + o.z * o.z + o.w * o.w;
            }
        }

        // register prefetch of raw operands for slab s+1 (hidden by GEMM)
        if (s + 1 < NSLAB) {
            const int hg1 = hh0 + CH + ch4;
            xv_p = __ldcs((const float4*)(xrow + hg1));
            #pragma unroll
            for (int j = 0; j < 4; j++)
                rv_p[j] = __ldcs((const float4*)(rrow + (size_t)j * NH + hg1));
        }

        __pipeline_wait_prior(0);   // fn slab s landed (this thread)
        __syncthreads();            // all threads: fn(s) visible, outS[st] ready,
                                    // GEMM(s-1) done -> safe to refill fnS[st^1]

        // ---- B phase: prefetch fn slab s+1, then GEMM on slab s
        if (s + 1 < NSLAB) {
            const int hh1 = hh0 + CH;
            #pragma unroll
            for (int k = 0; k < 6; k++) {
                int i4 = tid + k * 256;
                int m  = i4 >> 6;
                int c4 = (i4 & 63) << 2;
                __pipeline_memcpy_async(&fnS[st ^ 1][m][c4],
                    fn + (size_t)m * HCD + (c4 >> 6) * NH + hh1 + (c4 & 63), 16);
            }
            __pipeline_commit();
        }

        // GEMM micro: acc[r][mm] += outS[st][row][d] * fnS[st][m][d]
        #pragma unroll
        for (int dd = 0; dd < 2; dd++) {
            const int d0 = dp * 8 + dd * 4;
            float4 o[4];
            #pragma unroll
            for (int r = 0; r < 4; r++)
                o[r] = *(const float4*)&outS[st][rg * 4 + r][d0 ^ (rg << 2)];
            #pragma unroll
            for (int mm = 0; mm < 12; mm++) {
                float4 f = *(const float4*)&fnS[st][mg * 12 + mm][d0];
                #pragma unroll
                for (int r = 0; r < 4; r++)
                    acc[r][mm] += o[r].x * f.x + o[r].y * f.y + o[r].z * f.z + o[r].w * f.w;
            }
        }
    }

    // --- dot reductions: sum over dp (warp bits 3,4 via shuffle; warps via smem)
    #pragma unroll
    for (int r = 0; r < 4; r++)
        #pragma unroll
        for (int mm = 0; mm < 12; mm++) {
            float v = acc[r][mm];
            v += __shfl_xor_sync(0xffffffffu, v, 8);
            v += __shfl_xor_sync(0xffffffffu, v, 16);
            acc[r][mm] = v;
        }
    __syncthreads();   // everyone done reading outS before red overlay writes
    if ((tid & 24) == 0) {
        const int w = tid >> 5;
        #pragma unroll
        for (int r = 0; r < 4; r++)
            #pragma unroll
            for (int mm = 0; mm < 12; mm++)
                red[(mg * 12 + mm) * 16 + rg * 4 + r][w] = acc[r][mm];
    }
    __syncthreads();
    for (int o = tid; o < 384; o += 256) {
        float v = 0.f;
        #pragma unroll
        for (int w = 0; w < 8; w++) v += red[o][w];
        const int m = o >> 4, r = o & 15;
        g_lp[blockIdx.y][b0 + r][m] = v;
    }

    // --- sumsq: 16 lanes share crow
    float v = ssq;
    v += __shfl_xor_sync(0xffffffffu, v, 1);
    v += __shfl_xor_sync(0xffffffffu, v, 2);
    v += __shfl_xor_sync(0xffffffffu, v, 4);
    v += __shfl_xor_sync(0xffffffffu, v, 8);
    if ((tid & 15) == 0) g_ssq[blockIdx.y][bg] = v;
}

// ---------------------------------------------------------------------------
// Pass 2: per-row finalize — rms, softmax, sigmoid, Sinkhorn. One thread / row.
// ---------------------------------------------------------------------------
__global__ __launch_bounds__(256) void k_mid(
    const float* __restrict__ base, const float* __restrict__ scale,
    float* __restrict__ out)
{
    const int b = blockIdx.x * 256 + threadIdx.x;
    if (b >= NB) return;

    float lg[MIX];
    #pragma unroll
    for (int m = 0; m < MIX; m++)
        lg[m] = g_lp[0][b][m] + g_lp[1][b][m] + g_lp[2][b][m] + g_lp[3][b][m];
    const float ss = g_ssq[0][b] + g_ssq[1][b] + g_ssq[2][b] + g_ssq[3][b];
    const float inv = rsqrtf(ss * (1.0f / HCD) + 1e-6f);

    const float s0 = scale[0], s1 = scale[1], s2 = scale[2];

    // h_pre = softmax(logits[:4]*s0 + base[:4])
    float pre[4], mx = -1e30f;
    #pragma unroll
    for (int i = 0; i < 4; i++) {
        pre[i] = lg[i] * inv * s0 + base[i];
        mx = fmaxf(mx, pre[i]);
    }
    float e[4], den = 0.f;
    #pragma unroll
    for (int i = 0; i < 4; i++) { e[i] = expf(pre[i] - mx); den += e[i]; }
    const float rden = 1.f / den;
    #pragma unroll
    for (int i = 0; i < 4; i++) g_hpre[b][i] = e[i] * rden;

    // post_mix = sigmoid(logits[4:8]*s1 + base[4:8])
    #pragma unroll
    for (int i = 0; i < 4; i++) {
        const float p = lg[4 + i] * inv * s1 + base[4 + i];
        out[POST_OFF + (size_t)b * 4 + i] = 1.f / (1.f + expf(-p));
    }

    // comb_mix: Sinkhorn-Knopp on exp(logits[8:24]*s2 + base[8:24])
    float M[4][4];
    #pragma unroll
    for (int i = 0; i < 4; i++)
        #pragma unroll
        for (int j = 0; j < 4; j++)
            M[i][j] = expf(lg[8 + i * 4 + j] * inv * s2 + base[8 + i * 4 + j]);
    #pragma unroll
    for (int it = 0; it < 10; it++) {
        #pragma unroll
        for (int i = 0; i < 4; i++) {
            const float r = 1.f / (M[i][0] + M[i][1] + M[i][2] + M[i][3] + 1e-6f);
            #pragma unroll
            for (int j = 0; j < 4; j++) M[i][j] *= r;
        }
        #pragma unroll
        for (int j = 0; j < 4; j++) {
            const float c = 1.f / (M[0][j] + M[1][j] + M[2][j] + M[3][j] + 1e-6f);
            #pragma unroll
            for (int i = 0; i < 4; i++) M[i][j] *= c;
        }
    }
    #pragma unroll
    for (int i = 0; i < 4; i++)
        #pragma unroll
        for (int j = 0; j < 4; j++)
            out[COMB_OFF + (size_t)b * 16 + i * 4 + j] = M[i][j];
}

// ---------------------------------------------------------------------------
// Pass 3: layer_input[b,h] = sum_n h_pre[b,n] * residual_cur[b,n,h]
// ---------------------------------------------------------------------------
__global__ __launch_bounds__(256) void k_layer(float* __restrict__ out)
{
    const int b = blockIdx.x;
    const int h = (blockIdx.y * 256 + threadIdx.x) << 2;
    const float h0 = g_hpre[b][0], h1 = g_hpre[b][1];
    const float h2 = g_hpre[b][2], h3 = g_hpre[b][3];
    const float* rp = out + RES_OFF + (size_t)b * 4 * NH;
    const float4 a0 = __ldcs((const float4*)(rp + h));
    const float4 a1 = __ldcs((const float4*)(rp + NH + h));
    const float4 a2 = __ldcs((const float4*)(rp + 2 * NH + h));
    const float4 a3 = __ldcs((const float4*)(rp + 3 * NH + h));
    float4 o;
    o.x = h0 * a0.x + h1 * a1.x + h2 * a2.x + h3 * a3.x;
    o.y = h0 * a0.y + h1 * a1.y + h2 * a2.y + h3 * a3.y;
    o.z = h0 * a0.z + h1 * a1.z + h2 * a2.z + h3 * a3.z;
    o.w = h0 * a0.w + h1 * a1.w + h2 * a2.w + h3 * a3.w;
    __stcs((float4*)(out + LAYER_OFF + (size_t)b * NH + h), o);
}

extern "C" void kernel_launch(void* const* d_in, const int* in_sizes, int n_in,
                              void* d_out, int out_size)
{
    const float* x     = (const float*)d_in[0];
    const float* rprev = (const float*)d_in[1];
    const float* postp = (const float*)d_in[2];
    const float* combp = (const float*)d_in[3];
    const float* fn    = (const float*)d_in[4];
    const float* base  = (const float*)d_in[5];
    const float* scale = (const float*)d_in[6];
    float* out = (float*)d_out;

    cudaFuncSetAttribute(k_pass1, cudaFuncAttributeMaxDynamicSharedMemorySize, SMEM_DYN);
    k_pass1<<<dim3(NB / BM, NH / HR), 256, SMEM_DYN>>>(x, rprev, postp, combp, fn, out);
    k_mid<<<NB / 256, 256>>>(base, scale, out);
    k_layer<<<dim3(NB, NH / 1024), 256>>>(out);
}